// round 16
// baseline (speedup 1.0000x reference)
#include <cuda_runtime.h>
#include <cuda_bf16.h>
#include <cstdint>

#define KK 27
#define CENTER 13
#define NK 26                 // off-center offsets
#define NMAX 1000000
#define SLAB_SHIFT 17
#define SLAB (1 << SLAB_SHIFT)   // per-k pair capacity (max expected ~60K)

// ---------------- device scratch (no allocations allowed) ----------------
__device__ __align__(16) __nv_bfloat16 g_t0[(size_t)NMAX * 32]; // 64 MB
__device__ __align__(16) __nv_bfloat16 g_t1[(size_t)NMAX * 8];  // 16 MB
__device__ __align__(16) __nv_bfloat16 g_t2[(size_t)NMAX * 8];  // 16 MB
__device__ float g_Wc[KK * 8 * 32];          // tile-folded Wd0
__device__ __align__(16) int2 g_pairs[NK * SLAB];  // (dst, src) per-k fixed slabs
__device__ int   g_cursor[NK];               // per-k pair count
__device__ int   g_maskbyte;

__device__ __forceinline__ int y2k(int y) { return y < CENTER ? y : y + 1; }

// ---------------- precompute ----------------
__global__ void k_detect(const unsigned int* maskw, int N) {
    if (threadIdx.x == 0 && blockIdx.x == 0) {
        // center slab (k=13) is all-true by construction; byte layout => 0x01010101
        unsigned int w = maskw[((size_t)CENTER * N) / 4];
        g_maskbyte = (w == 0x01010101u) ? 1 : 0;
        for (int y = 0; y < NK; y++) g_cursor[y] = 0;
    }
}

// single-pass compaction: 4 voxels/thread, warp prefix, ONE atomic per block per k
__global__ void __launch_bounds__(256) k_fill(const void* mask, const int* __restrict__ nbr, int N) {
    int y = blockIdx.y, k = y2k(y);
    int i0 = (blockIdx.x * 256 + threadIdx.x) * 4;
    bool v[4] = {false, false, false, false};
    int4 nb = make_int4(0, 0, 0, 0);
    int cnt = 0;
    if (i0 + 3 < N) {
        size_t base = (size_t)k * N + i0;
        if (g_maskbyte) {
            uchar4 mv = *(const uchar4*)((const unsigned char*)mask + base);
            v[0] = mv.x; v[1] = mv.y; v[2] = mv.z; v[3] = mv.w;
        } else {
            int4 mv = *(const int4*)((const int*)mask + base);
            v[0] = mv.x; v[1] = mv.y; v[2] = mv.z; v[3] = mv.w;
        }
        nb = *(const int4*)(nbr + base);
    } else if (i0 < N) {
        size_t base = (size_t)k * N + i0;
        int* nbp = (int*)&nb;
        for (int j = 0; j < 4 && i0 + j < N; j++) {
            v[j] = g_maskbyte ? (((const unsigned char*)mask)[base + j] != 0)
                              : (((const int*)mask)[base + j] != 0);
            if (v[j]) nbp[j] = nbr[base + j];
        }
    }
    cnt = v[0] + v[1] + v[2] + v[3];

    int lane = threadIdx.x & 31, wid = threadIdx.x >> 5;
    int pre = cnt;
    #pragma unroll
    for (int o = 1; o < 32; o <<= 1) {
        int t = __shfl_up_sync(0xFFFFFFFFu, pre, o);
        if (lane >= o) pre += t;
    }
    int wtot = __shfl_sync(0xFFFFFFFFu, pre, 31);
    int excl = pre - cnt;

    __shared__ int wbase[8];
    __shared__ int bbase;
    if (lane == 31) wbase[wid] = wtot;
    __syncthreads();
    if (threadIdx.x == 0) {
        int s = 0;
        #pragma unroll
        for (int w = 0; w < 8; w++) { int t = wbase[w]; wbase[w] = s; s += t; }
        bbase = s ? atomicAdd(&g_cursor[y], s) : 0;
    }
    __syncthreads();

    if (cnt) {
        int p = bbase + wbase[wid] + excl;
        int slab = y << SLAB_SHIFT;
        const int* nbp = (const int*)&nb;
        #pragma unroll
        for (int j = 0; j < 4; j++)
            if (v[j]) {
                if (p < SLAB) g_pairs[slab + p] = make_int2(i0 + j, nbp[j]);
                p++;
            }
    }
}

// fold tile(x,4): Wc[k][ci8][co] = sum_t Wd0[k][ci8 + 8t][co]
__global__ void k_collapse(const float* __restrict__ Wd0) {
    int i = blockIdx.x * blockDim.x + threadIdx.x;
    if (i >= KK * 8 * 32) return;
    int co = i & 31, ci = (i >> 5) & 7, k = i >> 8;
    const float* Wk = Wd0 + k * 32 * 32;
    g_Wc[i] = Wk[ci * 32 + co] + Wk[(ci + 8) * 32 + co] +
              Wk[(ci + 16) * 32 + co] + Wk[(ci + 24) * 32 + co];
}

// ---------------- row load/store helpers ----------------
__device__ __forceinline__ uint32_t packbf(float a, float b) {
    __nv_bfloat162 h = __float22bfloat162_rn(make_float2(a, b));
    return *reinterpret_cast<uint32_t*>(&h);
}

template <int CIN, bool BF>
__device__ __forceinline__ void load_row(const void* __restrict__ in, int row, float* xr) {
    if constexpr (BF) {
        const uint4* p = reinterpret_cast<const uint4*>(
            reinterpret_cast<const __nv_bfloat16*>(in) + (size_t)row * CIN);
        #pragma unroll
        for (int j = 0; j < CIN / 8; j++) {
            uint4 v = p[j];
            uint32_t u[4] = {v.x, v.y, v.z, v.w};
            #pragma unroll
            for (int q = 0; q < 4; q++) {
                __nv_bfloat162 h = *reinterpret_cast<__nv_bfloat162*>(&u[q]);
                float2 f = __bfloat1622float2(h);
                xr[j * 8 + q * 2]     = f.x;
                xr[j * 8 + q * 2 + 1] = f.y;
            }
        }
    } else {
        const float4* p = reinterpret_cast<const float4*>(
            reinterpret_cast<const float*>(in) + (size_t)row * CIN);
        #pragma unroll
        for (int j = 0; j < CIN / 4; j++) {
            float4 v = p[j];
            xr[4 * j] = v.x; xr[4 * j + 1] = v.y; xr[4 * j + 2] = v.z; xr[4 * j + 3] = v.w;
        }
    }
}

template <int COUT, bool BF>
__device__ __forceinline__ void store_row(void* __restrict__ out, int row, const float* acc) {
    if constexpr (BF) {
        uint4* p = reinterpret_cast<uint4*>(
            reinterpret_cast<__nv_bfloat16*>(out) + (size_t)row * COUT);
        #pragma unroll
        for (int j = 0; j < COUT / 8; j++) {
            uint4 v;
            v.x = packbf(acc[j * 8 + 0], acc[j * 8 + 1]);
            v.y = packbf(acc[j * 8 + 2], acc[j * 8 + 3]);
            v.z = packbf(acc[j * 8 + 4], acc[j * 8 + 5]);
            v.w = packbf(acc[j * 8 + 6], acc[j * 8 + 7]);
            p[j] = v;
        }
    } else {
        float4* p = reinterpret_cast<float4*>(
            reinterpret_cast<float*>(out) + (size_t)row * COUT);
        #pragma unroll
        for (int j = 0; j < COUT / 4; j++)
            p[j] = make_float4(acc[4 * j], acc[4 * j + 1], acc[4 * j + 2], acc[4 * j + 3]);
    }
}

// REDs: v2.bf16x2 (8B) and v4.f32 (16B) ONLY — v4.bf16x2 regressed 6.5x in R13.
template <int COUT, bool BF>
__device__ __forceinline__ void red_row(void* __restrict__ out, int row, const float* acc) {
    if constexpr (BF) {
        __nv_bfloat16* p = reinterpret_cast<__nv_bfloat16*>(out) + (size_t)row * COUT;
        #pragma unroll
        for (int c = 0; c < COUT; c += 4) {
            uint32_t r0 = packbf(acc[c],     acc[c + 1]);
            uint32_t r1 = packbf(acc[c + 2], acc[c + 3]);
            asm volatile("red.global.add.noftz.v2.bf16x2 [%0], {%1,%2};"
                         :: "l"(p + c), "r"(r0), "r"(r1) : "memory");
        }
    } else {
        float* p = reinterpret_cast<float*>(out) + (size_t)row * COUT;
        #pragma unroll
        for (int c = 0; c < COUT; c += 4) {
            asm volatile("red.global.add.v4.f32 [%0], {%1,%2,%3,%4};"
                         :: "l"(p + c), "f"(acc[c]), "f"(acc[c + 1]),
                            "f"(acc[c + 2]), "f"(acc[c + 3]) : "memory");
        }
    }
}

template <int CIN, int COUT>
__device__ __forceinline__ void gemv(const float* Ws, const float* xr, float* acc) {
    #pragma unroll
    for (int ci = 0; ci < CIN; ci++) {
        float xv = xr[ci];
        #pragma unroll
        for (int c4 = 0; c4 < COUT / 4; c4++) {
            float4 w = *reinterpret_cast<const float4*>(&Ws[ci * COUT + c4 * 4]); // uniform -> smem broadcast
            acc[c4 * 4 + 0] += xv * w.x;
            acc[c4 * 4 + 1] += xv * w.y;
            acc[c4 * 4 + 2] += xv * w.z;
            acc[c4 * 4 + 3] += xv * w.w;
        }
    }
}

// ---------------- dense center pass: center offset IS the identity (k=13 => src=n, mask=true) ----
// MODE 0: acc = 0; MODE 1/2: acc = (tiled) x[n]
template <int CIN, int COUT, bool INBF, bool OUTBF, int MODE, int SGN>
__global__ void __launch_bounds__(256)
k_dense(const void* __restrict__ in, const float* __restrict__ x,
        const float* __restrict__ W, void* __restrict__ out, int N)
{
    __shared__ __align__(16) float Ws[CIN * COUT];
    for (int i = threadIdx.x; i < CIN * COUT; i += 256)
        Ws[i] = W[CENTER * CIN * COUT + i];
    __syncthreads();

    int n = blockIdx.x * 256 + threadIdx.x;
    if (n >= N) return;

    float acc[COUT];
    if constexpr (MODE == 0) {
        #pragma unroll
        for (int c = 0; c < COUT; c++) acc[c] = 0.f;
    } else {
        const float4* xp = reinterpret_cast<const float4*>(x + (size_t)n * 8);
        float4 a = xp[0], b = xp[1];
        float xb[8] = {a.x, a.y, a.z, a.w, b.x, b.y, b.z, b.w};
        #pragma unroll
        for (int c = 0; c < COUT; c++) acc[c] = xb[c & 7];
    }

    float xr[CIN];
    load_row<CIN, INBF>(in, n, xr);
    if constexpr (SGN < 0) {
        #pragma unroll
        for (int j = 0; j < CIN; j++) xr[j] = -xr[j];
    }
    gemv<CIN, COUT>(Ws, xr, acc);
    store_row<COUT, OUTBF>(out, n, acc);
}

// ---------------- k-partitioned scatter (thread-per-pair; used for COUT=8) ----------
template <int CIN, int COUT, bool INBF, bool OUTBF, int SGN, int PP>
__global__ void __launch_bounds__(256)
k_scatter(const void* __restrict__ in, const float* __restrict__ W, void* __restrict__ out)
{
    __shared__ __align__(16) float Ws[CIN * COUT];
    int y = blockIdx.y, k = y2k(y);
    for (int i = threadIdx.x; i < CIN * COUT; i += 256)
        Ws[i] = W[k * CIN * COUT + i];
    __syncthreads();

    const int2* pairs = g_pairs + ((size_t)y << SLAB_SHIFT);
    int cnt = g_cursor[y];
    if (cnt > SLAB) cnt = SLAB;

    for (int i = blockIdx.x * (256 * PP) + threadIdx.x; i < cnt; i += gridDim.x * (256 * PP)) {
        int2 e[PP];
        bool h[PP];
        #pragma unroll
        for (int p = 0; p < PP; p++) {
            int ii = i + p * 256;
            h[p] = ii < cnt;
            e[p] = pairs[h[p] ? ii : i];
        }
        float xr[PP][CIN];
        #pragma unroll
        for (int p = 0; p < PP; p++)
            load_row<CIN, INBF>(in, e[p].y, xr[p]);        // independent gathers -> MLP = PP
        #pragma unroll
        for (int p = 0; p < PP; p++) {
            if (!h[p]) continue;
            if constexpr (SGN < 0) {
                #pragma unroll
                for (int j = 0; j < CIN; j++) xr[p][j] = -xr[p][j];
            }
            float acc[COUT];
            #pragma unroll
            for (int c = 0; c < COUT; c++) acc[c] = 0.f;
            gemv<CIN, COUT>(Ws, xr[p], acc);
            red_row<COUT, OUTBF>(out, e[p].x, acc);
        }
    }
}

// ---------------- channel-split scatter for COUT=32: 8 lanes per pair, 4 pairs per warp ----
// lane = (g, c): g = lane>>3 selects pair, c = lane&7 selects channels [4c, 4c+4).
// RED per pair becomes ONE contiguous 32B(bf16)/128B(f32) span -> ~1 wavefront/pair (was 8).
template <int CIN, bool INBF, bool OUTBF>
__global__ void __launch_bounds__(256)
k_scatter32(const void* __restrict__ in, const float* __restrict__ W, void* __restrict__ out)
{
    __shared__ __align__(16) float Ws[CIN * 32];
    int y = blockIdx.y, k = y2k(y);
    for (int i = threadIdx.x; i < CIN * 32; i += 256)
        Ws[i] = W[k * CIN * 32 + i];
    __syncthreads();

    int lane = threadIdx.x & 31;
    int warp = threadIdx.x >> 5;
    int g = lane >> 3;          // pair-in-quad
    int c = lane & 7;           // channel chunk

    const int2* pairs = g_pairs + ((size_t)y << SLAB_SHIFT);
    int cnt = g_cursor[y];
    if (cnt > SLAB) cnt = SLAB;

    int step = gridDim.x * 8 * 4;   // warps * 4 pairs each
    for (int base = (blockIdx.x * 8 + warp) * 4; base < cnt; base += step) {
        int pi = base + g;
        bool valid = pi < cnt;
        int2 e = pairs[valid ? pi : base];   // 8 lanes/group share one address -> broadcast

        float xr[CIN];
        load_row<CIN, INBF>(in, e.y, xr);    // group-broadcast gather

        float4 acc = make_float4(0.f, 0.f, 0.f, 0.f);
        #pragma unroll
        for (int ci = 0; ci < CIN; ci++) {
            float4 w = *reinterpret_cast<const float4*>(&Ws[ci * 32 + c * 4]);  // conflict-free
            acc.x += xr[ci] * w.x;
            acc.y += xr[ci] * w.y;
            acc.z += xr[ci] * w.z;
            acc.w += xr[ci] * w.w;
        }

        if (valid) {
            if constexpr (OUTBF) {
                __nv_bfloat16* p = reinterpret_cast<__nv_bfloat16*>(out) + (size_t)e.x * 32 + c * 4;
                uint32_t r0 = packbf(acc.x, acc.y);
                uint32_t r1 = packbf(acc.z, acc.w);
                asm volatile("red.global.add.noftz.v2.bf16x2 [%0], {%1,%2};"
                             :: "l"(p), "r"(r0), "r"(r1) : "memory");
            } else {
                float* p = reinterpret_cast<float*>(out) + (size_t)e.x * 32 + c * 4;
                asm volatile("red.global.add.v4.f32 [%0], {%1,%2,%3,%4};"
                             :: "l"(p), "f"(acc.x), "f"(acc.y), "f"(acc.z), "f"(acc.w) : "memory");
            }
        }
    }
}

// ---------------- launch ----------------
extern "C" void kernel_launch(void* const* d_in, const int* in_sizes, int n_in,
                              void* d_out, int out_size)
{
    const float* x    = (const float*)d_in[0];   // [N,8]
    const int*   nbr  = (const int*)  d_in[1];   // [27,N]
    const void*  mask =               d_in[2];   // [27,N] bool (dtype auto-detected)
    const float* Wd0  = (const float*)d_in[3];   // [27,32,32]
    const float* Wd1  = (const float*)d_in[4];   // [27,32,8]
    const float* Wd2  = (const float*)d_in[5];   // [27,8,8]
    const float* Wu0  = (const float*)d_in[6];   // [27,8,8]
    const float* Wu1  = (const float*)d_in[7];   // [27,8,32]
    const float* Wu2  = (const float*)d_in[8];   // [27,32,32]
    float* out = (float*)d_out;
    int N = in_sizes[0] / 8;

    void *t0, *t1, *t2; float* Wc;
    cudaGetSymbolAddress(&t0, g_t0);
    cudaGetSymbolAddress(&t1, g_t1);
    cudaGetSymbolAddress(&t2, g_t2);
    cudaGetSymbolAddress((void**)&Wc, g_Wc);

    // precompute pair slabs (single pass; reused by all 6 convs)
    k_detect<<<1, 32>>>((const unsigned int*)mask, N);
    dim3 fg((N / 4 + 255) / 256, NK);
    k_fill<<<fg, 256>>>(mask, nbr, N);
    k_collapse<<<(KK * 8 * 32 + 255) / 256, 256>>>(Wd0);

    int db = (N + 255) / 256;
    dim3 sg4(64, NK);    // thread-per-pair, PP=4
    dim3 sg2(128, NK);   // thread-per-pair, PP=2
    dim3 cs(128, NK);    // channel-split: 128 blocks * 32 pairs/iter

    // c1: x -> t0   (tile-folded Wd0: effective 8->32)
    k_dense    <8, 32, false, true, 0, 1>   <<<db, 256>>>(x, x, Wc, t0, N);
    k_scatter32<8,     false, true>         <<<cs, 256>>>(x, Wc, t0);
    // c2: t0 -> t1  (Wd1: 32->8)
    k_dense    <32, 8, true, true, 0,  1>   <<<db, 256>>>(t0, x, Wd1, t1, N);
    k_scatter  <32, 8, true, true,     1, 2><<<sg2, 256>>>(t0, Wd1, t1);
    // c3: t1 -> t2 = x - conv(t1)  (Wd2: 8->8, negated contributions)
    k_dense    <8, 8, true, true, 1,  -1>   <<<db, 256>>>(t1, x, Wd2, t2, N);
    k_scatter  <8, 8, true, true,     -1, 4><<<sg4, 256>>>(t1, Wd2, t2);
    // c4: t2 -> t1  (Wu0: 8->8)
    k_dense    <8, 8, true, true, 0,   1>   <<<db, 256>>>(t2, x, Wu0, t1, N);
    k_scatter  <8, 8, true, true,      1, 4><<<sg4, 256>>>(t2, Wu0, t1);
    // c5: t1 -> t0  (Wu1: 8->32)
    k_dense    <8, 32, true, true, 0,  1>   <<<db, 256>>>(t1, x, Wu1, t0, N);
    k_scatter32<8,     true, true>          <<<cs, 256>>>(t1, Wu1, t0);
    // c6: t0 -> out = tile(x) + conv(t0)  (Wu2: 32->32, f32 out)
    k_dense    <32, 32, true, false, 2, 1>  <<<db, 256>>>(t0, x, Wu2, out, N);
    k_scatter32<32,     true, false>        <<<cs, 256>>>(t0, Wu2, out);
}

// round 17
// speedup vs baseline: 1.1002x; 1.1002x over previous
#include <cuda_runtime.h>
#include <cuda_bf16.h>
#include <cstdint>

#define KK 27
#define CENTER 13
#define NK 26                 // off-center offsets
#define NMAX 1000000
#define SLAB_SHIFT 17
#define SLAB (1 << SLAB_SHIFT)   // per-k pair capacity (max expected ~60K)

// ---------------- device scratch (no allocations allowed) ----------------
__device__ __align__(16) __nv_bfloat16 g_t0[(size_t)NMAX * 32]; // 64 MB
__device__ __align__(16) __nv_bfloat16 g_t1[(size_t)NMAX * 8];  // 16 MB
__device__ __align__(16) __nv_bfloat16 g_t2[(size_t)NMAX * 8];  // 16 MB
__device__ float g_Wc[KK * 8 * 32];          // tile-folded Wd0
__device__ __align__(16) int2 g_pairs[NK * SLAB];  // (dst, src) per-k fixed slabs
__device__ int   g_cursor[NK];               // per-k pair count
__device__ int   g_maskbyte;

__device__ __forceinline__ int y2k(int y) { return y < CENTER ? y : y + 1; }

// ---------------- f32x2 packed-math primitives (FFMA2: PTX-only on sm_103a) ----------------
__device__ __forceinline__ uint64_t splat2(float x) {
    uint64_t r; asm("mov.b64 %0, {%1, %1};" : "=l"(r) : "f"(x)); return r;
}
__device__ __forceinline__ uint64_t pack2(float a, float b) {
    uint64_t r; asm("mov.b64 %0, {%1, %2};" : "=l"(r) : "f"(a), "f"(b)); return r;
}
__device__ __forceinline__ void unpack2(uint64_t v, float& a, float& b) {
    asm("mov.b64 {%0, %1}, %2;" : "=f"(a), "=f"(b) : "l"(v));
}
__device__ __forceinline__ uint64_t fma2(uint64_t a, uint64_t b, uint64_t c) {
    uint64_t d; asm("fma.rn.f32x2 %0, %1, %2, %3;" : "=l"(d) : "l"(a), "l"(b), "l"(c)); return d;
}

// ---------------- precompute ----------------
__global__ void k_detect(const unsigned int* maskw, int N) {
    if (threadIdx.x == 0 && blockIdx.x == 0) {
        // center slab (k=13) is all-true by construction; byte layout => 0x01010101
        unsigned int w = maskw[((size_t)CENTER * N) / 4];
        g_maskbyte = (w == 0x01010101u) ? 1 : 0;
        for (int y = 0; y < NK; y++) g_cursor[y] = 0;
    }
}

// single-pass compaction: 4 voxels/thread, warp prefix, ONE atomic per block per k
__global__ void __launch_bounds__(256) k_fill(const void* mask, const int* __restrict__ nbr, int N) {
    int y = blockIdx.y, k = y2k(y);
    int i0 = (blockIdx.x * 256 + threadIdx.x) * 4;
    bool v[4] = {false, false, false, false};
    int4 nb = make_int4(0, 0, 0, 0);
    int cnt = 0;
    if (i0 + 3 < N) {
        size_t base = (size_t)k * N + i0;
        if (g_maskbyte) {
            uchar4 mv = *(const uchar4*)((const unsigned char*)mask + base);
            v[0] = mv.x; v[1] = mv.y; v[2] = mv.z; v[3] = mv.w;
        } else {
            int4 mv = *(const int4*)((const int*)mask + base);
            v[0] = mv.x; v[1] = mv.y; v[2] = mv.z; v[3] = mv.w;
        }
        nb = *(const int4*)(nbr + base);
    } else if (i0 < N) {
        size_t base = (size_t)k * N + i0;
        int* nbp = (int*)&nb;
        for (int j = 0; j < 4 && i0 + j < N; j++) {
            v[j] = g_maskbyte ? (((const unsigned char*)mask)[base + j] != 0)
                              : (((const int*)mask)[base + j] != 0);
            if (v[j]) nbp[j] = nbr[base + j];
        }
    }
    cnt = v[0] + v[1] + v[2] + v[3];

    int lane = threadIdx.x & 31, wid = threadIdx.x >> 5;
    int pre = cnt;
    #pragma unroll
    for (int o = 1; o < 32; o <<= 1) {
        int t = __shfl_up_sync(0xFFFFFFFFu, pre, o);
        if (lane >= o) pre += t;
    }
    int wtot = __shfl_sync(0xFFFFFFFFu, pre, 31);
    int excl = pre - cnt;

    __shared__ int wbase[8];
    __shared__ int bbase;
    if (lane == 31) wbase[wid] = wtot;
    __syncthreads();
    if (threadIdx.x == 0) {
        int s = 0;
        #pragma unroll
        for (int w = 0; w < 8; w++) { int t = wbase[w]; wbase[w] = s; s += t; }
        bbase = s ? atomicAdd(&g_cursor[y], s) : 0;
    }
    __syncthreads();

    if (cnt) {
        int p = bbase + wbase[wid] + excl;
        int slab = y << SLAB_SHIFT;
        const int* nbp = (const int*)&nb;
        #pragma unroll
        for (int j = 0; j < 4; j++)
            if (v[j]) {
                if (p < SLAB) g_pairs[slab + p] = make_int2(i0 + j, nbp[j]);
                p++;
            }
    }
}

// fold tile(x,4): Wc[k][ci8][co] = sum_t Wd0[k][ci8 + 8t][co]
__global__ void k_collapse(const float* __restrict__ Wd0) {
    int i = blockIdx.x * blockDim.x + threadIdx.x;
    if (i >= KK * 8 * 32) return;
    int co = i & 31, ci = (i >> 5) & 7, k = i >> 8;
    const float* Wk = Wd0 + k * 32 * 32;
    g_Wc[i] = Wk[ci * 32 + co] + Wk[(ci + 8) * 32 + co] +
              Wk[(ci + 16) * 32 + co] + Wk[(ci + 24) * 32 + co];
}

// ---------------- row load/store helpers ----------------
__device__ __forceinline__ uint32_t packbf(float a, float b) {
    __nv_bfloat162 h = __float22bfloat162_rn(make_float2(a, b));
    return *reinterpret_cast<uint32_t*>(&h);
}

template <int CIN, bool BF>
__device__ __forceinline__ void load_row(const void* __restrict__ in, int row, float* xr) {
    if constexpr (BF) {
        const uint4* p = reinterpret_cast<const uint4*>(
            reinterpret_cast<const __nv_bfloat16*>(in) + (size_t)row * CIN);
        #pragma unroll
        for (int j = 0; j < CIN / 8; j++) {
            uint4 v = p[j];
            uint32_t u[4] = {v.x, v.y, v.z, v.w};
            #pragma unroll
            for (int q = 0; q < 4; q++) {
                __nv_bfloat162 h = *reinterpret_cast<__nv_bfloat162*>(&u[q]);
                float2 f = __bfloat1622float2(h);
                xr[j * 8 + q * 2]     = f.x;
                xr[j * 8 + q * 2 + 1] = f.y;
            }
        }
    } else {
        const float4* p = reinterpret_cast<const float4*>(
            reinterpret_cast<const float*>(in) + (size_t)row * CIN);
        #pragma unroll
        for (int j = 0; j < CIN / 4; j++) {
            float4 v = p[j];
            xr[4 * j] = v.x; xr[4 * j + 1] = v.y; xr[4 * j + 2] = v.z; xr[4 * j + 3] = v.w;
        }
    }
}

// store from PACKED acc (COUT/2 x u64)
template <int COUT, bool BF>
__device__ __forceinline__ void store_row2(void* __restrict__ out, int row, const uint64_t* acc) {
    float f[COUT];
    #pragma unroll
    for (int j = 0; j < COUT / 2; j++) unpack2(acc[j], f[2 * j], f[2 * j + 1]);
    if constexpr (BF) {
        uint4* p = reinterpret_cast<uint4*>(
            reinterpret_cast<__nv_bfloat16*>(out) + (size_t)row * COUT);
        #pragma unroll
        for (int j = 0; j < COUT / 8; j++) {
            uint4 v;
            v.x = packbf(f[j * 8 + 0], f[j * 8 + 1]);
            v.y = packbf(f[j * 8 + 2], f[j * 8 + 3]);
            v.z = packbf(f[j * 8 + 4], f[j * 8 + 5]);
            v.w = packbf(f[j * 8 + 6], f[j * 8 + 7]);
            p[j] = v;
        }
    } else {
        float4* p = reinterpret_cast<float4*>(
            reinterpret_cast<float*>(out) + (size_t)row * COUT);
        #pragma unroll
        for (int j = 0; j < COUT / 4; j++)
            p[j] = make_float4(f[4 * j], f[4 * j + 1], f[4 * j + 2], f[4 * j + 3]);
    }
}

// RED from PACKED acc. v2.bf16x2 (8B) and v4.f32 (16B) ONLY — v4.bf16x2 regressed 6.5x in R13.
template <int COUT, bool BF>
__device__ __forceinline__ void red_row2(void* __restrict__ out, int row, const uint64_t* acc) {
    float f[COUT];
    #pragma unroll
    for (int j = 0; j < COUT / 2; j++) unpack2(acc[j], f[2 * j], f[2 * j + 1]);
    if constexpr (BF) {
        __nv_bfloat16* p = reinterpret_cast<__nv_bfloat16*>(out) + (size_t)row * COUT;
        #pragma unroll
        for (int c = 0; c < COUT; c += 4) {
            uint32_t r0 = packbf(f[c],     f[c + 1]);
            uint32_t r1 = packbf(f[c + 2], f[c + 3]);
            asm volatile("red.global.add.noftz.v2.bf16x2 [%0], {%1,%2};"
                         :: "l"(p + c), "r"(r0), "r"(r1) : "memory");
        }
    } else {
        float* p = reinterpret_cast<float*>(out) + (size_t)row * COUT;
        #pragma unroll
        for (int c = 0; c < COUT; c += 4) {
            asm volatile("red.global.add.v4.f32 [%0], {%1,%2,%3,%4};"
                         :: "l"(p + c), "f"(f[c]), "f"(f[c + 1]),
                            "f"(f[c + 2]), "f"(f[c + 3]) : "memory");
        }
    }
}

// packed gemv: 1 pair, acc[COUT/2] u64; weight LDS.128 carries two f32x2
template <int CIN, int COUT>
__device__ __forceinline__ void gemv2(const float* Ws, const float* xr, uint64_t* acc) {
    #pragma unroll
    for (int ci = 0; ci < CIN; ci++) {
        uint64_t xv = splat2(xr[ci]);
        #pragma unroll
        for (int j = 0; j < COUT / 4; j++) {
            ulonglong2 w = *reinterpret_cast<const ulonglong2*>(&Ws[ci * COUT + j * 4]);
            acc[j * 2]     = fma2(xv, w.x, acc[j * 2]);
            acc[j * 2 + 1] = fma2(xv, w.y, acc[j * 2 + 1]);
        }
    }
}

// packed gemv over PP pairs: weight LDS amortized across pairs
template <int CIN, int COUT, int PP>
__device__ __forceinline__ void gemv2_multi(const float* Ws, const float xr[][CIN],
                                            uint64_t acc[][COUT / 2]) {
    #pragma unroll
    for (int ci = 0; ci < CIN; ci++) {
        uint64_t xv[PP];
        #pragma unroll
        for (int p = 0; p < PP; p++) xv[p] = splat2(xr[p][ci]);
        #pragma unroll
        for (int j = 0; j < COUT / 4; j++) {
            ulonglong2 w = *reinterpret_cast<const ulonglong2*>(&Ws[ci * COUT + j * 4]);
            #pragma unroll
            for (int p = 0; p < PP; p++) {
                acc[p][j * 2]     = fma2(xv[p], w.x, acc[p][j * 2]);
                acc[p][j * 2 + 1] = fma2(xv[p], w.y, acc[p][j * 2 + 1]);
            }
        }
    }
}

// ---------------- dense center pass: center offset IS the identity (k=13 => src=n, mask=true) ----
// MODE 0: acc = 0; MODE 1/2: acc = (tiled) x[n]
template <int CIN, int COUT, bool INBF, bool OUTBF, int MODE, int SGN>
__global__ void __launch_bounds__(256)
k_dense(const void* __restrict__ in, const float* __restrict__ x,
        const float* __restrict__ W, void* __restrict__ out, int N)
{
    __shared__ __align__(16) float Ws[CIN * COUT];
    for (int i = threadIdx.x; i < CIN * COUT; i += 256)
        Ws[i] = W[CENTER * CIN * COUT + i];
    __syncthreads();

    int n = blockIdx.x * 256 + threadIdx.x;
    if (n >= N) return;

    uint64_t acc[COUT / 2];
    if constexpr (MODE == 0) {
        #pragma unroll
        for (int j = 0; j < COUT / 2; j++) acc[j] = 0ULL;
    } else {
        const float4* xp = reinterpret_cast<const float4*>(x + (size_t)n * 8);
        float4 a = xp[0], b = xp[1];
        uint64_t pk[4] = {pack2(a.x, a.y), pack2(a.z, a.w), pack2(b.x, b.y), pack2(b.z, b.w)};
        #pragma unroll
        for (int j = 0; j < COUT / 2; j++) acc[j] = pk[j & 3];
    }

    float xr[CIN];
    load_row<CIN, INBF>(in, n, xr);
    if constexpr (SGN < 0) {
        #pragma unroll
        for (int j = 0; j < CIN; j++) xr[j] = -xr[j];
    }
    gemv2<CIN, COUT>(Ws, xr, acc);
    store_row2<COUT, OUTBF>(out, n, acc);
}

// ---------------- k-partitioned scatter (thread-per-pair, strided PP, packed math) ----------
template <int CIN, int COUT, bool INBF, bool OUTBF, int SGN, int PP>
__global__ void __launch_bounds__(256)
k_scatter(const void* __restrict__ in, const float* __restrict__ W, void* __restrict__ out)
{
    __shared__ __align__(16) float Ws[CIN * COUT];
    int y = blockIdx.y, k = y2k(y);
    for (int i = threadIdx.x; i < CIN * COUT; i += 256)
        Ws[i] = W[k * CIN * COUT + i];
    __syncthreads();

    const int2* pairs = g_pairs + ((size_t)y << SLAB_SHIFT);
    int cnt = g_cursor[y];
    if (cnt > SLAB) cnt = SLAB;

    for (int i = blockIdx.x * (256 * PP) + threadIdx.x; i < cnt; i += gridDim.x * (256 * PP)) {
        int2 e[PP];
        bool h[PP];
        #pragma unroll
        for (int p = 0; p < PP; p++) {
            int ii = i + p * 256;
            h[p] = ii < cnt;
            e[p] = pairs[h[p] ? ii : i];
        }
        float xr[PP][CIN];
        #pragma unroll
        for (int p = 0; p < PP; p++)
            load_row<CIN, INBF>(in, e[p].y, xr[p]);        // independent gathers -> MLP = PP
        if constexpr (SGN < 0) {
            #pragma unroll
            for (int p = 0; p < PP; p++)
                #pragma unroll
                for (int j = 0; j < CIN; j++) xr[p][j] = -xr[p][j];
        }
        uint64_t acc[PP][COUT / 2];
        #pragma unroll
        for (int p = 0; p < PP; p++)
            #pragma unroll
            for (int j = 0; j < COUT / 2; j++) acc[p][j] = 0ULL;
        gemv2_multi<CIN, COUT, PP>(Ws, xr, acc);
        #pragma unroll
        for (int p = 0; p < PP; p++)
            if (h[p]) red_row2<COUT, OUTBF>(out, e[p].x, acc[p]);
    }
}

// ---------------- launch ----------------
extern "C" void kernel_launch(void* const* d_in, const int* in_sizes, int n_in,
                              void* d_out, int out_size)
{
    const float* x    = (const float*)d_in[0];   // [N,8]
    const int*   nbr  = (const int*)  d_in[1];   // [27,N]
    const void*  mask =               d_in[2];   // [27,N] bool (dtype auto-detected)
    const float* Wd0  = (const float*)d_in[3];   // [27,32,32]
    const float* Wd1  = (const float*)d_in[4];   // [27,32,8]
    const float* Wd2  = (const float*)d_in[5];   // [27,8,8]
    const float* Wu0  = (const float*)d_in[6];   // [27,8,8]
    const float* Wu1  = (const float*)d_in[7];   // [27,8,32]
    const float* Wu2  = (const float*)d_in[8];   // [27,32,32]
    float* out = (float*)d_out;
    int N = in_sizes[0] / 8;

    void *t0, *t1, *t2; float* Wc;
    cudaGetSymbolAddress(&t0, g_t0);
    cudaGetSymbolAddress(&t1, g_t1);
    cudaGetSymbolAddress(&t2, g_t2);
    cudaGetSymbolAddress((void**)&Wc, g_Wc);

    // precompute pair slabs (single pass; reused by all 6 convs)
    k_detect<<<1, 32>>>((const unsigned int*)mask, N);
    dim3 fg((N / 4 + 255) / 256, NK);
    k_fill<<<fg, 256>>>(mask, nbr, N);
    k_collapse<<<(KK * 8 * 32 + 255) / 256, 256>>>(Wd0);

    int db = (N + 255) / 256;
    dim3 sg4(64, NK);    // PP=4: 64*1024 = 65536 slots per k
    dim3 sg2(128, NK);   // PP=2: 128*512 = 65536 slots per k

    // c1: x -> t0   (tile-folded Wd0: effective 8->32)
    k_dense  <8, 32, false, true, 0,  1>   <<<db, 256>>>(x, x, Wc, t0, N);
    k_scatter<8, 32, false, true,     1, 4><<<sg4, 256>>>(x, Wc, t0);
    // c2: t0 -> t1  (Wd1: 32->8)
    k_dense  <32, 8, true, true, 0,   1>   <<<db, 256>>>(t0, x, Wd1, t1, N);
    k_scatter<32, 8, true, true,      1, 2><<<sg2, 256>>>(t0, Wd1, t1);
    // c3: t1 -> t2 = x - conv(t1)  (Wd2: 8->8, negated contributions)
    k_dense  <8, 8, true, true, 1,   -1>   <<<db, 256>>>(t1, x, Wd2, t2, N);
    k_scatter<8, 8, true, true,      -1, 4><<<sg4, 256>>>(t1, Wd2, t2);
    // c4: t2 -> t1  (Wu0: 8->8)
    k_dense  <8, 8, true, true, 0,    1>   <<<db, 256>>>(t2, x, Wu0, t1, N);
    k_scatter<8, 8, true, true,       1, 4><<<sg4, 256>>>(t2, Wu0, t1);
    // c5: t1 -> t0  (Wu1: 8->32)
    k_dense  <8, 32, true, true, 0,   1>   <<<db, 256>>>(t1, x, Wu1, t0, N);
    k_scatter<8, 32, true, true,      1, 4><<<sg4, 256>>>(t1, Wu1, t0);
    // c6: t0 -> out = tile(x) + conv(t0)  (Wu2: 32->32, f32 out)
    k_dense  <32, 32, true, false, 2, 1>   <<<db, 256>>>(t0, x, Wu2, out, N);
    k_scatter<32, 32, true, false,    1, 2><<<sg2, 256>>>(t0, Wu2, out);
}